// round 17
// baseline (speedup 1.0000x reference)
#include <cuda_runtime.h>
#include <cuda_fp16.h>

#define D_IN  128
#define D_OUT 64
#define MAX_NODES 50000
#define RPB 64    // rows per block (gemm)

// scratch: h = x @ W stored fp16 (6.4 MB), CSR row pointers
__device__ __half g_h[MAX_NODES * D_OUT];
__device__ int    g_row_ptr[MAX_NODES + 1];

// ---------------------------------------------------------------------------
// CSR row offsets via boundary detection, 16 edges per thread (4x int4, MLP=4).
// ---------------------------------------------------------------------------
__global__ void rowptr_kernel(const int* __restrict__ dst,
                              int n_edges, int n_nodes) {
    int t  = blockIdx.x * blockDim.x + threadIdx.x;
    int e0 = t << 4;
    if (e0 >= n_edges) return;

    int d[17];
    d[0] = (e0 == 0) ? -1 : __ldg(dst + e0 - 1);

    if (e0 + 16 <= n_edges) {
        int4 q0 = __ldg((const int4*)(dst + e0));
        int4 q1 = __ldg((const int4*)(dst + e0 + 4));
        int4 q2 = __ldg((const int4*)(dst + e0 + 8));
        int4 q3 = __ldg((const int4*)(dst + e0 + 12));
        d[1]=q0.x; d[2]=q0.y; d[3]=q0.z; d[4]=q0.w;
        d[5]=q1.x; d[6]=q1.y; d[7]=q1.z; d[8]=q1.w;
        d[9]=q2.x; d[10]=q2.y; d[11]=q2.z; d[12]=q2.w;
        d[13]=q3.x; d[14]=q3.y; d[15]=q3.z; d[16]=q3.w;
    } else {
        #pragma unroll
        for (int j = 0; j < 16; j++)
            d[j + 1] = (e0 + j < n_edges) ? __ldg(dst + e0 + j) : d[j];
    }

    #pragma unroll
    for (int j = 0; j < 16; j++) {
        int ee = e0 + j;
        if (ee < n_edges)
            for (int i = d[j] + 1; i <= d[j + 1]; i++) g_row_ptr[i] = ee;
    }
    if (e0 + 16 >= n_edges) {
        int last = d[16];
        for (int i = last + 1; i <= n_nodes; i++) g_row_ptr[i] = n_edges;
    }
}

// ---------------------------------------------------------------------------
// h = x @ W, mma.m16n8k16 fp16, fp32 accum, ldmatrix fragments (R16).
// SINGLE CHANGE vs R16: W staged with coalesced float4 LDG (8/thread)
// + transposed STS.16, replacing 32 strided scalar LDGs per thread.
// ---------------------------------------------------------------------------
__global__ void __launch_bounds__(256)
gemm_kernel(const float* __restrict__ x,
            const float* __restrict__ w,
            int n_nodes) {
    __shared__ __half Xs[RPB][136];     // 17.4 KB
    __shared__ __half Wt[D_OUT][136];   // 17.4 KB  (W transposed: [n][k])

    int tid   = threadIdx.x;
    int lane  = tid & 31;
    int warp  = tid >> 5;
    int row0  = blockIdx.x * RPB;
    int g     = lane >> 2;          // 0..7
    int tig   = lane & 3;           // 0..3
    int wrow  = (warp >> 1) * 16;   // m-tile base row within block
    int nhalf = (warp & 1) * 32;    // n-half base col
    int lrow  = lane & 7;           // ldmatrix row-in-group
    int seg   = lane >> 3;          // ldmatrix segment 0..3

    // stage x panel: 64 rows x 128 k, fp32 -> fp16
    for (int i = tid; i < RPB * 32; i += 256) {
        int r = i >> 5, q = i & 31;
        int gr = row0 + r;
        float4 v = make_float4(0.f, 0.f, 0.f, 0.f);
        if (gr < n_nodes)
            v = __ldg((const float4*)(x + (size_t)gr * D_IN + q * 4));
        __half2* p = (__half2*)&Xs[r][q * 4];
        p[0] = __floats2half2_rn(v.x, v.y);
        p[1] = __floats2half2_rn(v.z, v.w);
    }
    // stage W transposed: coalesced float4 loads (8 per thread), STS.16
    for (int i = tid; i < D_IN * 16; i += 256) {
        int r = i >> 4, q = i & 15;     // r = k, q = col-quad
        float4 v = __ldg((const float4*)(w + r * D_OUT + q * 4));
        Wt[q * 4 + 0][r] = __float2half_rn(v.x);
        Wt[q * 4 + 1][r] = __float2half_rn(v.y);
        Wt[q * 4 + 2][r] = __float2half_rn(v.z);
        Wt[q * 4 + 3][r] = __float2half_rn(v.w);
    }
    __syncthreads();

    float acc[4][4];
    #pragma unroll
    for (int nt = 0; nt < 4; nt++)
        #pragma unroll
        for (int c = 0; c < 4; c++) acc[nt][c] = 0.f;

    #pragma unroll
    for (int ks = 0; ks < 8; ks++) {
        int kc = ks * 16;

        // A fragment via ldmatrix.x4: segments {M00,M10,M01,M11}
        unsigned a0, a1, a2, a3;
        {
            const __half* ap = &Xs[wrow + (seg & 1) * 8 + lrow][kc + (seg >> 1) * 8];
            unsigned sa = (unsigned)__cvta_generic_to_shared(ap);
            asm volatile(
                "ldmatrix.sync.aligned.m8n8.x4.shared.b16 {%0,%1,%2,%3}, [%4];"
                : "=r"(a0), "=r"(a1), "=r"(a2), "=r"(a3) : "r"(sa));
        }

        #pragma unroll
        for (int nt = 0; nt < 4; nt++) {
            int col0 = nhalf + nt * 8;
            unsigned b0, b1;
            {
                const __half* bp = &Wt[col0 + lrow][kc + (seg & 1) * 8];
                unsigned sb = (unsigned)__cvta_generic_to_shared(bp);
                asm volatile(
                    "ldmatrix.sync.aligned.m8n8.x2.shared.b16 {%0,%1}, [%2];"
                    : "=r"(b0), "=r"(b1) : "r"(sb));
            }
            asm volatile(
                "mma.sync.aligned.m16n8k16.row.col.f32.f16.f16.f32 "
                "{%0,%1,%2,%3},{%4,%5,%6,%7},{%8,%9},{%0,%1,%2,%3};"
                : "+f"(acc[nt][0]), "+f"(acc[nt][1]),
                  "+f"(acc[nt][2]), "+f"(acc[nt][3])
                : "r"(a0), "r"(a1), "r"(a2), "r"(a3),
                  "r"(b0), "r"(b1));
        }
    }

    // epilogue: (c0,c1)@(row=g, col=2tig), (c2,c3)@(row=g+8)
    int r0 = row0 + wrow + g;
    #pragma unroll
    for (int nt = 0; nt < 4; nt++) {
        int c0 = nhalf + nt * 8 + 2 * tig;
        if (r0 < n_nodes)
            *(__half2*)(g_h + (size_t)r0 * D_OUT + c0) =
                __floats2half2_rn(acc[nt][0], acc[nt][1]);
        if (r0 + 8 < n_nodes)
            *(__half2*)(g_h + (size_t)(r0 + 8) * D_OUT + c0) =
                __floats2half2_rn(acc[nt][2], acc[nt][3]);
    }
}

// ---------------------------------------------------------------------------
// 4-nodes-per-warp aggregation.  SINGLE CHANGE vs R14/R16: 4-edge unroll
// per subgroup (MLP 2 -> 4 on the gather chain; 16 lines in flight per
// warp).  Lane sl owns cols [8sl, 8sl+7] (one uint4 of the fp16 h-row).
// ---------------------------------------------------------------------------
__global__ void __launch_bounds__(256)
gather_kernel(const int*   __restrict__ src,
              const float* __restrict__ vals,
              const float* __restrict__ bias,
              float*       __restrict__ out,
              int n_nodes) {
    int warp = (blockIdx.x * 256 + threadIdx.x) >> 5;
    int lane = threadIdx.x & 31;
    int sub  = lane >> 3;      // 0..3 subgroup
    int sl   = lane & 7;       // 0..7 lane-in-subgroup
    int node = warp * 4 + sub;
    if (node >= n_nodes) return;

    int e0 = g_row_ptr[node];
    int e1 = g_row_ptr[node + 1];

    float acc[8];
    #pragma unroll
    for (int c = 0; c < 8; c++) acc[c] = 0.f;

    int e = e0;
    for (; e + 4 <= e1; e += 4) {
        int s[4]; float v[4];
        #pragma unroll
        for (int j = 0; j < 4; j++) { s[j] = __ldg(src + e + j); v[j] = __ldg(vals + e + j); }
        uint4 h[4];
        #pragma unroll
        for (int j = 0; j < 4; j++)
            h[j] = *(const uint4*)(g_h + ((size_t)s[j] << 6) + (sl << 3));
        #pragma unroll
        for (int j = 0; j < 4; j++) {
            const __half2* p = (const __half2*)&h[j];
            #pragma unroll
            for (int q = 0; q < 4; q++) {
                float2 f = __half22float2(p[q]);
                acc[2 * q]     += v[j] * f.x;
                acc[2 * q + 1] += v[j] * f.y;
            }
        }
    }
    for (; e < e1; e++) {
        int   s0 = __ldg(src + e);
        float v0 = __ldg(vals + e);
        uint4 h0 = *(const uint4*)(g_h + ((size_t)s0 << 6) + (sl << 3));
        const __half2* p0 = (const __half2*)&h0;
        #pragma unroll
        for (int q = 0; q < 4; q++) {
            float2 f0 = __half22float2(p0[q]);
            acc[2 * q]     += v0 * f0.x;
            acc[2 * q + 1] += v0 * f0.y;
        }
    }

    float4 b0 = __ldg((const float4*)(bias + (sl << 3)));
    float4 b1 = __ldg((const float4*)(bias + (sl << 3) + 4));
    float* o = out + ((size_t)node << 6) + (sl << 3);
    *(float4*)(o)     = make_float4(acc[0] + b0.x, acc[1] + b0.y,
                                    acc[2] + b0.z, acc[3] + b0.w);
    *(float4*)(o + 4) = make_float4(acc[4] + b1.x, acc[5] + b1.y,
                                    acc[6] + b1.z, acc[7] + b1.w);
}

// ---------------------------------------------------------------------------
extern "C" void kernel_launch(void* const* d_in, const int* in_sizes, int n_in,
                              void* d_out, int out_size) {
    const float* x     = (const float*)d_in[0];
    const int*   esrc  = (const int*)  d_in[1];
    const int*   edst  = (const int*)  d_in[2];
    const float* evals = (const float*)d_in[3];
    const float* w     = (const float*)d_in[4];
    const float* bias  = (const float*)d_in[5];
    float*       out   = (float*)d_out;

    int n_nodes = in_sizes[0] / D_IN;
    int n_edges = in_sizes[1];

    gemm_kernel<<<(n_nodes + RPB - 1) / RPB, 256>>>(x, w, n_nodes);

    int nt = (n_edges + 15) / 16;
    rowptr_kernel<<<(nt + 255) / 256, 256>>>(edst, n_edges, n_nodes);

    int warps = (n_nodes + 3) / 4;
    gather_kernel<<<(warps * 32 + 255) / 256, 256>>>(esrc, evals, bias, out, n_nodes);
}